// round 3
// baseline (speedup 1.0000x reference)
#include <cuda_runtime.h>
#include <math.h>

#define BATCH 64
#define C     128
#define OC    128
#define H     80
#define W     80
#define POOL  5      // k+2
#define TS    16     // spatial tile (16x16 outputs per block)
#define OCT   64     // output channels per block
#define ICC   8      // input-channel chunk
#define PITCH 20     // smem input row pitch (18 used, padded)

// Scratch (allocation-free rule: __device__ globals)
__device__ float g_avg[BATCH * C * POOL * POOL];            // [b][c][5][5]
__device__ float g_dynw[BATCH * OC * C * 9];                // [b][oc][ic][3][3]

// ---------------------------------------------------------------------------
// Kernel A: adaptive average pool 80x80 -> 5x5 (16x16 equal tiles)
// one thread per output cell
// ---------------------------------------------------------------------------
__global__ void avgpool_kernel(const float* __restrict__ x) {
    int idx = blockIdx.x * blockDim.x + threadIdx.x;
    if (idx >= BATCH * C * POOL * POOL) return;
    int cell = idx % (POOL * POOL);
    int bc   = idx / (POOL * POOL);
    int oy = cell / POOL, ox = cell % POOL;
    const float* p = x + ((long)bc * H + oy * 16) * W + ox * 16;
    float s = 0.f;
    #pragma unroll
    for (int r = 0; r < 16; r++) {
        const float4* q = (const float4*)(p + r * W);
        #pragma unroll
        for (int j = 0; j < 4; j++) {
            float4 v = q[j];
            s += v.x + v.y + v.z + v.w;
        }
    }
    g_avg[idx] = s * (1.f / 256.f);
}

// ---------------------------------------------------------------------------
// Kernel B: attention conv (3x3 VALID on 5x5) + sigmoid + weight modulation
// one thread per (b, oc, ic); dynamic weight layout [b][oc][ic][3][3]
// ---------------------------------------------------------------------------
__global__ void att_kernel(const float* __restrict__ weight,
                           const float* __restrict__ w_att,
                           const float* __restrict__ b_att) {
    int idx = blockIdx.x * blockDim.x + threadIdx.x;   // (b*OC + oc)*C + ic
    if (idx >= BATCH * OC * C) return;
    int ic  = idx % C;
    int boc = idx / C;              // b*OC + oc  (== b*C + oc since OC==C)
    int oc  = boc % OC;
    int o   = oc * C + ic;          // attention output channel

    float a[25];
    #pragma unroll
    for (int i = 0; i < 25; i++) a[i] = g_avg[boc * 25 + i];  // warp-broadcast
    float wa[9];
    #pragma unroll
    for (int i = 0; i < 9; i++) wa[i] = w_att[o * 9 + i];
    float bias = b_att[o];

    #pragma unroll
    for (int kh = 0; kh < 3; kh++) {
        #pragma unroll
        for (int kw = 0; kw < 3; kw++) {
            float s = bias;
            #pragma unroll
            for (int i = 0; i < 3; i++)
                #pragma unroll
                for (int j = 0; j < 3; j++)
                    s += a[(kh + i) * 5 + (kw + j)] * wa[i * 3 + j];
            float sig = 1.f / (1.f + expf(-s));
            int tap = kh * 3 + kw;
            g_dynw[(long)idx * 9 + tap] = weight[(oc * C + ic) * 9 + tap] * sig;
        }
    }
}

// ---------------------------------------------------------------------------
// Kernel C: main conv, per-sample dynamic weights, 3x3, pad 1
// block = (spatial 16x16 tile) x (64 oc) x (1 batch)
// thread micro-tile = 8 oc x 8 pixels (pixels strided by 32 within tile)
// ---------------------------------------------------------------------------
__global__ void __launch_bounds__(256, 2)
conv_kernel(const float* __restrict__ x, float* __restrict__ out) {
    __shared__ float s_in[ICC][18 * PITCH];     // 8*18*20*4 = 11.5 KB
    __shared__ float s_w[ICC][9][OCT];          // 8*9*64*4  = 18.4 KB

    const int tid = threadIdx.x;
    const int tx  = tid & 31;        // lane
    const int ty  = tid >> 5;        // oc group 0..7
    const int b   = blockIdx.z;
    const int oc0 = blockIdx.y * OCT;
    const int gy0 = (blockIdx.x / (W / TS)) * TS;
    const int gx0 = (blockIdx.x % (W / TS)) * TS;

    const int pxl    = tx & 15;      // pixel x within tile
    const int pyBase = tx >> 4;      // 0 or 1; pixel rows = pyBase + 2*i

    float acc[8][8];
    #pragma unroll
    for (int o = 0; o < 8; o++)
        #pragma unroll
        for (int i = 0; i < 8; i++) acc[o][i] = 0.f;

    const float* xb = x + (long)b * C * H * W;
    const float* wb = g_dynw + ((long)(b * OC + oc0)) * C * 9;

    for (int ic0 = 0; ic0 < C; ic0 += ICC) {
        __syncthreads();
        // load input tile [ICC][18][18] (global rows gy0-1..gy0+16)
        for (int t = tid; t < ICC * 18 * 18; t += 256) {
            int col = t % 18;
            int row = (t / 18) % 18;
            int ic  = t / (18 * 18);
            int gy = gy0 - 1 + row;
            int gx = gx0 - 1 + col;
            float v = 0.f;
            if (gy >= 0 && gy < H && gx >= 0 && gx < W)
                v = xb[((ic0 + ic) * H + gy) * W + gx];
            s_in[ic][row * PITCH + col] = v;
        }
        // load weights transposed: s_w[ic][tap][oc]
        for (int t = tid; t < OCT * ICC * 9; t += 256) {
            int tap = t % 9;
            int ic  = (t / 9) % ICC;
            int oc  = t / (9 * ICC);
            s_w[ic][tap][oc] = wb[(oc * C + ic0 + ic) * 9 + tap];
        }
        __syncthreads();

        #pragma unroll
        for (int ic = 0; ic < ICC; ic++) {
            #pragma unroll
            for (int kh = 0; kh < 3; kh++) {
                #pragma unroll
                for (int kw = 0; kw < 3; kw++) {
                    float inv[8];
                    const float* sp = &s_in[ic][(pyBase + kh) * PITCH + pxl + kw];
                    #pragma unroll
                    for (int i = 0; i < 8; i++) inv[i] = sp[i * 2 * PITCH];
                    float4 w0 = *(const float4*)&s_w[ic][kh * 3 + kw][ty * 8];
                    float4 w1 = *(const float4*)&s_w[ic][kh * 3 + kw][ty * 8 + 4];
                    float wv[8] = {w0.x, w0.y, w0.z, w0.w, w1.x, w1.y, w1.z, w1.w};
                    #pragma unroll
                    for (int o = 0; o < 8; o++)
                        #pragma unroll
                        for (int i = 0; i < 8; i++)
                            acc[o][i] += wv[o] * inv[i];
                }
            }
        }
    }

    // write 8 oc x 8 pixels
    #pragma unroll
    for (int o = 0; o < 8; o++) {
        int oc = oc0 + ty * 8 + o;
        float* op = out + ((long)(b * OC + oc) * H) * W;
        #pragma unroll
        for (int i = 0; i < 8; i++) {
            int py = pyBase + 2 * i;
            op[(gy0 + py) * W + gx0 + pxl] = acc[o][i];
        }
    }
}

// ---------------------------------------------------------------------------
extern "C" void kernel_launch(void* const* d_in, const int* in_sizes, int n_in,
                              void* d_out, int out_size) {
    const float* x      = (const float*)d_in[0];   // [64,128,80,80]
    const float* weight = (const float*)d_in[1];   // [128,128,3,3]
    const float* w_att  = (const float*)d_in[2];   // [16384,1,3,3]
    const float* b_att  = (const float*)d_in[3];   // [16384]
    float* out = (float*)d_out;                    // [64,128,80,80]

    {
        int n = BATCH * C * POOL * POOL;
        avgpool_kernel<<<(n + 255) / 256, 256>>>(x);
    }
    {
        int n = BATCH * OC * C;
        att_kernel<<<(n + 255) / 256, 256>>>(weight, w_att, b_att);
    }
    {
        dim3 grid((H / TS) * (W / TS), OC / OCT, BATCH);  // (25, 2, 64)
        conv_kernel<<<grid, 256>>>(x, out);
    }
}

// round 6
// speedup vs baseline: 1.9861x; 1.9861x over previous
#include <cuda_runtime.h>
#include <cstdint>
#include <math.h>

#define BATCH 64
#define CIN   128
#define OCH   128
#define H     80
#define W     80
#define HW    6400
#define MTILE 128            // pixels per CTA
#define NCHUNK 36            // 9 taps * 4 ic-chunks of 32

// Scratch (allocation-free rule: __device__ globals)
__device__ float g_avg[BATCH * CIN * 25];                 // [b][c][5][5]
__device__ float g_dynw[(size_t)BATCH * 9 * OCH * CIN];   // [b][tap][oc][ic], tf32-rounded

__device__ __forceinline__ uint32_t tf32r(float v) {
    uint32_t u;
    asm("cvt.rna.tf32.f32 %0, %1;" : "=r"(u) : "f"(v));
    return u;
}

__device__ __forceinline__ void mma_tf32(float* d, const uint32_t* a, const uint32_t* bq) {
    asm volatile(
        "mma.sync.aligned.m16n8k8.row.col.f32.tf32.tf32.f32 "
        "{%0,%1,%2,%3}, {%4,%5,%6,%7}, {%8,%9}, {%0,%1,%2,%3};"
        : "+f"(d[0]), "+f"(d[1]), "+f"(d[2]), "+f"(d[3])
        : "r"(a[0]), "r"(a[1]), "r"(a[2]), "r"(a[3]), "r"(bq[0]), "r"(bq[1]));
}

// ---------------------------------------------------------------------------
// Kernel A: adaptive average pool 80x80 -> 5x5 (16x16 equal tiles)
// ---------------------------------------------------------------------------
__global__ void avgpool_kernel(const float* __restrict__ x) {
    int idx = blockIdx.x * blockDim.x + threadIdx.x;
    if (idx >= BATCH * CIN * 25) return;
    int cell = idx % 25;
    int bc   = idx / 25;
    int oy = cell / 5, ox = cell % 5;
    const float* p = x + ((size_t)bc * H + oy * 16) * W + ox * 16;
    float s = 0.f;
    #pragma unroll
    for (int r = 0; r < 16; r++) {
        const float4* q = (const float4*)(p + r * W);
        #pragma unroll
        for (int j = 0; j < 4; j++) {
            float4 v = q[j];
            s += v.x + v.y + v.z + v.w;
        }
    }
    g_avg[idx] = s * (1.f / 256.f);
}

// ---------------------------------------------------------------------------
// Kernel B: attention conv (3x3 VALID on 5x5) + sigmoid + weight modulation
// Writes tf32-pre-rounded dynamic weights in layout [b][tap][oc][ic]
// ---------------------------------------------------------------------------
__global__ void att_kernel(const float* __restrict__ weight,
                           const float* __restrict__ w_att,
                           const float* __restrict__ b_att) {
    int idx = blockIdx.x * blockDim.x + threadIdx.x;   // (b*OCH + oc)*CIN + ic
    if (idx >= BATCH * OCH * CIN) return;
    int ic  = idx % CIN;
    int boc = idx / CIN;            // b*OCH + oc
    int oc  = boc % OCH;
    int b   = boc / OCH;
    int o   = oc * CIN + ic;        // attention output channel

    float a[25];
    #pragma unroll
    for (int i = 0; i < 25; i++) a[i] = g_avg[boc * 25 + i];
    float wa[9];
    #pragma unroll
    for (int i = 0; i < 9; i++) wa[i] = w_att[o * 9 + i];
    float bias = b_att[o];

    #pragma unroll
    for (int kh = 0; kh < 3; kh++) {
        #pragma unroll
        for (int kw = 0; kw < 3; kw++) {
            float s = bias;
            #pragma unroll
            for (int i = 0; i < 3; i++)
                #pragma unroll
                for (int j = 0; j < 3; j++)
                    s += a[(kh + i) * 5 + (kw + j)] * wa[i * 3 + j];
            float sig = 1.f / (1.f + expf(-s));
            int tap = kh * 3 + kw;
            float v = weight[(oc * CIN + ic) * 9 + tap] * sig;
            g_dynw[(((size_t)b * 9 + tap) * OCH + oc) * CIN + ic] = __uint_as_float(tf32r(v));
        }
    }
}

// ---------------------------------------------------------------------------
// Kernel C: tf32 mma.sync implicit-GEMM conv
// CTA: 128 pixels (M) x 128 oc (N); K = 9 taps x 128 ic in chunks of 32.
// SMEM holds operands pre-arranged in m16n8k8 fragment order:
//   sA[(mtile*4+kstep)*32 + lane] -> float4 {a0,a1,a2,a3}
//   sB[(ntile*4+kstep)*32 + lane] -> float2 {b0,b1}
// 8 warps: warp grid 2(M) x 4(N), warp tile 64x32, acc 4x4x4 per thread.
// Register double-buffer: LDG chunk j+1 into regs while MMA consumes chunk j.
// ---------------------------------------------------------------------------
__global__ void __launch_bounds__(256)
conv_kernel(const float* __restrict__ x, float* __restrict__ out) {
    __shared__ float sA[4096];   // 16 KB: 8 mtiles * 4 ksteps * 32 lanes * 4
    __shared__ float sB[4096];   // 16 KB: 16 ntiles * 4 ksteps * 32 lanes * 2

    const int tid  = threadIdx.x;
    const int lane = tid & 31, wid = tid >> 5;
    const int b    = blockIdx.y;
    const int n0   = blockIdx.x * MTILE;

    // ---- writer identities ----
    const int px   = tid & 127;          // pixel within CTA tile (A writer)
    const int ih   = tid >> 7;           // which 16-ic half this thread loads
    const int yA   = (n0 + px) / W, xxA = (n0 + px) % W;
    const int mtw  = px >> 4;            // A mtile
    const int rA   = px & 15, gA = rA & 7, rhalf = rA >> 3;
    const int ocB  = tid & 127;          // oc (B writer)
    const int ntw  = ocB >> 3, gB = ocB & 7;

    const float* xb    = x + (size_t)b * CIN * HW;
    const float* wbase = g_dynw + (size_t)b * 9 * OCH * CIN;

    // ---- mma identities ----
    const int warpM = wid & 1, warpN = wid >> 1;
    const int mtb = warpM * 4, ntb = warpN * 4;

    float acc[4][4][4];
    #pragma unroll
    for (int mf = 0; mf < 4; mf++)
        #pragma unroll
        for (int nf = 0; nf < 4; nf++)
            #pragma unroll
            for (int q = 0; q < 4; q++) acc[mf][nf][q] = 0.f;

    float areg[16];
    float breg[16];

    // ---- chunk loader (global -> regs) ----
    #define LOAD_CHUNK(J) do {                                                  \
        int _tap = (J) >> 2, _ic0 = ((J) & 3) * 32;                             \
        int _dy = _tap / 3 - 1, _dx = _tap % 3 - 1;                             \
        int _sy = yA + _dy, _sx = xxA + _dx;                                    \
        bool _ok = (_sy >= 0) & (_sy < H) & (_sx >= 0) & (_sx < W);             \
        const float* _ap = xb + (size_t)(_ic0 + ih * 16) * HW + _sy * W + _sx;  \
        _Pragma("unroll")                                                       \
        for (int c = 0; c < 16; c++) areg[c] = _ok ? __ldg(_ap + c * HW) : 0.f; \
        const float4* _wp = (const float4*)(wbase + ((size_t)_tap * OCH + ocB) * CIN + _ic0 + ih * 16); \
        _Pragma("unroll")                                                       \
        for (int q = 0; q < 4; q++) ((float4*)breg)[q] = __ldg(_wp + q);        \
    } while (0)

    LOAD_CHUNK(0);

    for (int j = 0; j < NCHUNK; j++) {
        __syncthreads();   // previous MMA phase done reading SMEM

        // ---- store regs -> SMEM in fragment order ----
        #pragma unroll
        for (int c = 0; c < 16; c++) {
            int cc = ih * 16 + c;
            int ks = cc >> 3, col = cc & 7, tig = col & 3, ch = col >> 2;
            sA[(((mtw * 4 + ks) * 32) + gA * 4 + tig) * 4 + rhalf + 2 * ch] =
                __uint_as_float(tf32r(areg[c]));
        }
        #pragma unroll
        for (int c = 0; c < 16; c++) {
            int cc = ih * 16 + c;
            int ks = cc >> 3, col = cc & 7, tig = col & 3, hh = col >> 2;
            sB[(((ntw * 4 + ks) * 32) + gB * 4 + tig) * 2 + hh] = breg[c];
        }
        __syncthreads();

        if (j + 1 < NCHUNK) LOAD_CHUNK(j + 1);   // prefetch overlaps MMA below

        // ---- MMA phase: 64 mma per warp per chunk ----
        #pragma unroll
        for (int ks = 0; ks < 4; ks++) {
            uint32_t bf[4][2];
            #pragma unroll
            for (int nf = 0; nf < 4; nf++) {
                float2 v = *(const float2*)&sB[(((ntb + nf) * 4 + ks) * 32 + lane) * 2];
                bf[nf][0] = __float_as_uint(v.x);
                bf[nf][1] = __float_as_uint(v.y);
            }
            #pragma unroll
            for (int mf = 0; mf < 4; mf++) {
                float4 a4 = *(const float4*)&sA[(((mtb + mf) * 4 + ks) * 32 + lane) * 4];
                uint32_t av[4] = {__float_as_uint(a4.x), __float_as_uint(a4.y),
                                  __float_as_uint(a4.z), __float_as_uint(a4.w)};
                #pragma unroll
                for (int nf = 0; nf < 4; nf++)
                    mma_tf32(acc[mf][nf], av, bf[nf]);
            }
        }
    }

    // ---- epilogue: regs -> GMEM (out[b][oc][pixel]) ----
    {
        const int g = lane >> 2, tg = lane & 3;
        #pragma unroll
        for (int mf = 0; mf < 4; mf++) {
            int pix = n0 + warpM * 64 + mf * 16 + g;
            #pragma unroll
            for (int nf = 0; nf < 4; nf++) {
                int oc = warpN * 32 + nf * 8 + tg * 2;
                float* o0 = out + (size_t)(b * OCH + oc) * HW;
                o0[pix]          = acc[mf][nf][0];
                o0[HW + pix]     = acc[mf][nf][1];
                o0[pix + 8]      = acc[mf][nf][2];
                o0[HW + pix + 8] = acc[mf][nf][3];
            }
        }
    }
}

// ---------------------------------------------------------------------------
extern "C" void kernel_launch(void* const* d_in, const int* in_sizes, int n_in,
                              void* d_out, int out_size) {
    const float* x      = (const float*)d_in[0];   // [64,128,80,80]
    const float* weight = (const float*)d_in[1];   // [128,128,3,3]
    const float* w_att  = (const float*)d_in[2];   // [16384,1,3,3]
    const float* b_att  = (const float*)d_in[3];   // [16384]
    float* out = (float*)d_out;                    // [64,128,80,80]

    {
        int ntot = BATCH * CIN * 25;
        avgpool_kernel<<<(ntot + 255) / 256, 256>>>(x);
    }
    {
        int ntot = BATCH * OCH * CIN;
        att_kernel<<<(ntot + 255) / 256, 256>>>(weight, w_att, b_att);
    }
    {
        dim3 grid(HW / MTILE, BATCH);   // (50, 64)
        conv_kernel<<<grid, 256>>>(x, out);
    }
}

// round 7
// speedup vs baseline: 2.9688x; 1.4948x over previous
#include <cuda_runtime.h>
#include <cstdint>
#include <math.h>

#define BATCH 64
#define CIN   128
#define OCH   128
#define H     80
#define W     80
#define HW    6400
#define MTILE 128            // pixels per CTA
#define NCHUNK 36            // 9 taps * 4 ic-chunks of 32

// Scratch (allocation-free rule: __device__ globals)
__device__ float g_avg[BATCH * CIN * 25];                 // [b][c][5][5]
__device__ float g_dynw[(size_t)BATCH * 9 * OCH * CIN];   // [b][tap][oc][ic], tf32-rounded

__device__ __forceinline__ uint32_t tf32r(float v) {
    uint32_t u;
    asm("cvt.rna.tf32.f32 %0, %1;" : "=r"(u) : "f"(v));
    return u;
}

__device__ __forceinline__ void mma_tf32(float* d, const uint32_t* a, const uint32_t* bq) {
    asm volatile(
        "mma.sync.aligned.m16n8k8.row.col.f32.tf32.tf32.f32 "
        "{%0,%1,%2,%3}, {%4,%5,%6,%7}, {%8,%9}, {%0,%1,%2,%3};"
        : "+f"(d[0]), "+f"(d[1]), "+f"(d[2]), "+f"(d[3])
        : "r"(a[0]), "r"(a[1]), "r"(a[2]), "r"(a[3]), "r"(bq[0]), "r"(bq[1]));
}

// fragment-index swizzles (bijective; applied identically on store & load)
__device__ __forceinline__ int swzA(int F) {
    return F ^ ((F >> 2) & 7) ^ (((F >> 7) & 1) << 1);
}
__device__ __forceinline__ int swzB(int G) {
    return G ^ ((G >> 2) & 7) ^ (((G >> 7) & 1) << 3);
}

// ---------------------------------------------------------------------------
// Kernel A: adaptive average pool 80x80 -> 5x5 (16x16 equal tiles)
// ---------------------------------------------------------------------------
__global__ void avgpool_kernel(const float* __restrict__ x) {
    int idx = blockIdx.x * blockDim.x + threadIdx.x;
    if (idx >= BATCH * CIN * 25) return;
    int cell = idx % 25;
    int bc   = idx / 25;
    int oy = cell / 5, ox = cell % 5;
    const float* p = x + ((size_t)bc * H + oy * 16) * W + ox * 16;
    float s = 0.f;
    #pragma unroll
    for (int r = 0; r < 16; r++) {
        const float4* q = (const float4*)(p + r * W);
        #pragma unroll
        for (int j = 0; j < 4; j++) {
            float4 v = q[j];
            s += v.x + v.y + v.z + v.w;
        }
    }
    g_avg[idx] = s * (1.f / 256.f);
}

// ---------------------------------------------------------------------------
// Kernel B: attention conv (3x3 VALID on 5x5) + sigmoid + weight modulation
// Writes tf32-pre-rounded dynamic weights in layout [b][tap][oc][ic]
// ---------------------------------------------------------------------------
__global__ void att_kernel(const float* __restrict__ weight,
                           const float* __restrict__ w_att,
                           const float* __restrict__ b_att) {
    int idx = blockIdx.x * blockDim.x + threadIdx.x;   // (b*OCH + oc)*CIN + ic
    if (idx >= BATCH * OCH * CIN) return;
    int ic  = idx % CIN;
    int boc = idx / CIN;            // b*OCH + oc
    int oc  = boc % OCH;
    int b   = boc / OCH;
    int o   = oc * CIN + ic;        // attention output channel

    float a[25];
    #pragma unroll
    for (int i = 0; i < 25; i++) a[i] = g_avg[boc * 25 + i];
    float wa[9];
    #pragma unroll
    for (int i = 0; i < 9; i++) wa[i] = w_att[o * 9 + i];
    float bias = b_att[o];

    #pragma unroll
    for (int kh = 0; kh < 3; kh++) {
        #pragma unroll
        for (int kw = 0; kw < 3; kw++) {
            float s = bias;
            #pragma unroll
            for (int i = 0; i < 3; i++)
                #pragma unroll
                for (int j = 0; j < 3; j++)
                    s += a[(kh + i) * 5 + (kw + j)] * wa[i * 3 + j];
            float sig = 1.f / (1.f + expf(-s));
            int tap = kh * 3 + kw;
            float v = weight[(oc * CIN + ic) * 9 + tap] * sig;
            g_dynw[(((size_t)b * 9 + tap) * OCH + oc) * CIN + ic] = __uint_as_float(tf32r(v));
        }
    }
}

// ---------------------------------------------------------------------------
// Kernel C: tf32 mma.sync implicit-GEMM conv
// CTA: 128 pixels (M) x 128 oc (N); K = 9 taps x 128 ic in chunks of 32.
// Fragment-order SMEM, double-buffered, XOR-swizzled for conflict-free STS/LDS:
//   A: float4 slot F (swzA), elements [a0,a2,a1,a3]  (slot = rhalf*2 + ch)
//   B: float2 slot G (swzB), elements [b0,b1]
// 8 warps: grid 2(M) x 4(N), warp tile 64x32. One __syncthreads per chunk.
// SMEM (dynamic, 64KB floats): [A0 4096][A1 4096][B0 4096][B1 4096]
// ---------------------------------------------------------------------------
__global__ void __launch_bounds__(256)
conv_kernel(const float* __restrict__ x, float* __restrict__ out) {
    extern __shared__ float smem[];

    const int tid  = threadIdx.x;
    const int lane = tid & 31, wid = tid >> 5;
    const int b    = blockIdx.y;
    const int n0   = blockIdx.x * MTILE;

    // ---- writer identities ----
    const int px   = tid & 127;          // pixel within CTA tile (A writer)
    const int ih   = tid >> 7;           // which 16-ic half this thread loads
    const int yA   = (n0 + px) / W, xxA = (n0 + px) % W;
    const int mtw  = px >> 4;            // A mtile (0..7)
    const int rA   = px & 15, gA = rA & 7, rhalf = rA >> 3;
    const int ocB  = tid & 127;          // oc (B writer)
    const int ntw  = ocB >> 3, gB = ocB & 7;

    const float* xb    = x + (size_t)b * CIN * HW;
    const float* wbase = g_dynw + (size_t)b * 9 * OCH * CIN;

    // ---- mma identities ----
    const int warpM = wid & 1, warpN = wid >> 1;
    const int mtb = warpM * 4, ntb = warpN * 4;

    float acc[4][4][4];
    #pragma unroll
    for (int mf = 0; mf < 4; mf++)
        #pragma unroll
        for (int nf = 0; nf < 4; nf++)
            #pragma unroll
            for (int q = 0; q < 4; q++) acc[mf][nf][q] = 0.f;

    float areg[16];
    float breg[16];

    // ---- chunk loader (global -> regs) ----
    #define LOAD_CHUNK(J) do {                                                  \
        int _tap = (J) >> 2, _ic0 = ((J) & 3) * 32;                             \
        int _dy = _tap / 3 - 1, _dx = _tap % 3 - 1;                             \
        int _sy = yA + _dy, _sx = xxA + _dx;                                    \
        bool _ok = (_sy >= 0) & (_sy < H) & (_sx >= 0) & (_sx < W);             \
        const float* _ap = xb + (size_t)(_ic0 + ih * 16) * HW + _sy * W + _sx;  \
        _Pragma("unroll")                                                       \
        for (int c = 0; c < 16; c++) areg[c] = _ok ? __ldg(_ap + c * HW) : 0.f; \
        const float4* _wp = (const float4*)(wbase + ((size_t)_tap * OCH + ocB) * CIN + _ic0 + ih * 16); \
        _Pragma("unroll")                                                       \
        for (int q = 0; q < 4; q++) ((float4*)breg)[q] = __ldg(_wp + q);        \
    } while (0)

    LOAD_CHUNK(0);

    for (int j = 0; j < NCHUNK; j++) {
        const int buf = j & 1;
        float* sA = smem + buf * 4096;
        float* sB = smem + 8192 + buf * 4096;

        // ---- STS: regs -> fragment-order SMEM (float2, swizzled) ----
        #pragma unroll
        for (int ksl = 0; ksl < 2; ksl++) {
            const int ks = ih * 2 + ksl;
            #pragma unroll
            for (int tig = 0; tig < 4; tig++) {
                // A: two values (ch=0, ch=1) -> contiguous slots rhalf*2, rhalf*2+1
                int F = (mtw * 4 + ks) * 32 + gA * 4 + tig;
                int Fs = swzA(F);
                float2 av2;
                av2.x = __uint_as_float(tf32r(areg[ksl * 8 + tig]));
                av2.y = __uint_as_float(tf32r(areg[ksl * 8 + tig + 4]));
                *(float2*)(sA + Fs * 4 + rhalf * 2) = av2;
                // B: {b0, b1}
                int G = (ntw * 4 + ks) * 32 + gB * 4 + tig;
                int Gs = swzB(G);
                float2 bv2;
                bv2.x = breg[ksl * 8 + tig];
                bv2.y = breg[ksl * 8 + tig + 4];
                *(float2*)(sB + Gs * 2) = bv2;
            }
        }
        __syncthreads();

        if (j + 1 < NCHUNK) LOAD_CHUNK(j + 1);   // prefetch overlaps MMA below

        // ---- MMA phase: 64 mma per warp per chunk ----
        #pragma unroll
        for (int ks = 0; ks < 4; ks++) {
            uint32_t bf[4][2];
            #pragma unroll
            for (int nf = 0; nf < 4; nf++) {
                int G = ((ntb + nf) * 4 + ks) * 32 + lane;
                float2 v = *(const float2*)(sB + swzB(G) * 2);
                bf[nf][0] = __float_as_uint(v.x);
                bf[nf][1] = __float_as_uint(v.y);
            }
            #pragma unroll
            for (int mf = 0; mf < 4; mf++) {
                int F = ((mtb + mf) * 4 + ks) * 32 + lane;
                float4 a4 = *(const float4*)(sA + swzA(F) * 4);
                // layout [a0,a2,a1,a3] -> mma order (a0,a1,a2,a3)
                uint32_t av[4] = {__float_as_uint(a4.x), __float_as_uint(a4.z),
                                  __float_as_uint(a4.y), __float_as_uint(a4.w)};
                #pragma unroll
                for (int nf = 0; nf < 4; nf++)
                    mma_tf32(acc[mf][nf], av, bf[nf]);
            }
        }
    }

    // ---- epilogue: regs -> GMEM (out[b][oc][pixel]) ----
    {
        const int g = lane >> 2, tg = lane & 3;
        #pragma unroll
        for (int mf = 0; mf < 4; mf++) {
            int pix = n0 + warpM * 64 + mf * 16 + g;
            #pragma unroll
            for (int nf = 0; nf < 4; nf++) {
                int oc = warpN * 32 + nf * 8 + tg * 2;
                float* o0 = out + (size_t)(b * OCH + oc) * HW;
                o0[pix]          = acc[mf][nf][0];
                o0[HW + pix]     = acc[mf][nf][1];
                o0[pix + 8]      = acc[mf][nf][2];
                o0[HW + pix + 8] = acc[mf][nf][3];
            }
        }
    }
}

#define CONV_SMEM_BYTES (4 * 4096 * 4)   // 64 KB

// ---------------------------------------------------------------------------
extern "C" void kernel_launch(void* const* d_in, const int* in_sizes, int n_in,
                              void* d_out, int out_size) {
    const float* x      = (const float*)d_in[0];   // [64,128,80,80]
    const float* weight = (const float*)d_in[1];   // [128,128,3,3]
    const float* w_att  = (const float*)d_in[2];   // [16384,1,3,3]
    const float* b_att  = (const float*)d_in[3];   // [16384]
    float* out = (float*)d_out;                    // [64,128,80,80]

    cudaFuncSetAttribute(conv_kernel, cudaFuncAttributeMaxDynamicSharedMemorySize,
                         CONV_SMEM_BYTES);

    {
        int ntot = BATCH * CIN * 25;
        avgpool_kernel<<<(ntot + 255) / 256, 256>>>(x);
    }
    {
        int ntot = BATCH * OCH * CIN;
        att_kernel<<<(ntot + 255) / 256, 256>>>(weight, w_att, b_att);
    }
    {
        dim3 grid(HW / MTILE, BATCH);   // (50, 64)
        conv_kernel<<<grid, 256, CONV_SMEM_BYTES>>>(x, out);
    }
}